// round 16
// baseline (speedup 1.0000x reference)
#include <cuda_runtime.h>
#include <cuda_fp16.h>
#include <cstdint>

static constexpr int T_TOK = 8192;
static constexpr int C_DIM = 2048;
static constexpr int KDIM = C_DIM;         // plain fp16 GEMM, K = 2048
static constexpr int BM = 128;
static constexpr int BN = 128;
static constexpr int BK = 64;              // fp16 per K-chunk (128B rows)
static constexpr int NKCH = KDIM / BK;     // 32
static constexpr int ROW_BYTES = 144;      // 128B data + 16B pad (conflict-free ldmatrix)
static constexpr int AROWS = BM;
static constexpr int STAGE_ROWS = BM + BN; // 256
static constexpr int STAGE_BYTES = STAGE_ROWS * ROW_BYTES;  // 36864
static constexpr int STAGES = 3;
static constexpr int GEMM_SMEM = STAGES * STAGE_BYTES;      // 110592 -> 2 CTAs/SM
static constexpr int GTHREADS = 256;       // 8 warps: 2 over M x 4 over N (64x32 tiles)

// -------- scratch (static __device__; no allocation allowed) --------
__device__ __half g_xs [(size_t)T_TOK * C_DIM];
__device__ __half g_ys [(size_t)T_TOK * C_DIM];
__device__ __half g_aos[(size_t)T_TOK * C_DIM];
__device__ __half g_wq [(size_t)C_DIM * C_DIM];
__device__ __half g_wkv[(size_t)(2 * C_DIM) * C_DIM];
__device__ __half g_wo [(size_t)C_DIM * C_DIM];
__device__ float g_q  [(size_t)T_TOK * C_DIM];
__device__ float g_kv [(size_t)T_TOK * 2 * C_DIM];
__device__ float g_bkv[2 * C_DIM];

// -------- PTX helpers (sm_80/sm_90 features only; no 'a'-suffix) --------
__device__ __forceinline__ uint32_t smem_u32(const void* p) {
    uint32_t a;
    asm("{ .reg .u64 t; cvta.to.shared.u64 t, %1; cvt.u32.u64 %0, t; }" : "=r"(a) : "l"(p));
    return a;
}
#define CP_ASYNC16(s, g) \
    asm volatile("cp.async.cg.shared.global [%0], [%1], 16;" :: "r"((uint32_t)(s)), "l"(g) : "memory")

#define LDSM4(r, addr) \
    asm volatile("ldmatrix.sync.aligned.m8n8.x4.shared.b16 {%0,%1,%2,%3}, [%4];" \
        : "=r"((r)[0]), "=r"((r)[1]), "=r"((r)[2]), "=r"((r)[3]) : "r"(addr))

#define MMA16816(d, a, b0, b1) \
    asm volatile("mma.sync.aligned.m16n8k16.row.col.f32.f16.f16.f32 " \
        "{%0,%1,%2,%3}, {%4,%5,%6,%7}, {%8,%9}, {%0,%1,%2,%3};" \
        : "+f"((d)[0]), "+f"((d)[1]), "+f"((d)[2]), "+f"((d)[3]) \
        : "r"((a)[0]), "r"((a)[1]), "r"((a)[2]), "r"((a)[3]), "r"(b0), "r"(b1))

#define MBARRIER_INIT(m, c) \
    asm volatile("mbarrier.init.shared.b64 [%0], %1;" :: "r"((uint32_t)(m)), "r"((uint32_t)(c)) : "memory")
#define MBARRIER_ARRIVE(m) \
    asm volatile("mbarrier.arrive.shared.b64 _, [%0];" :: "r"((uint32_t)(m)) : "memory")
// .noinc: this arrival counts against the init count (pre-counted async arrive).
// Without .noinc the pending count self-increments and the phase NEVER completes (R15 hang).
#define CP_ASYNC_MBAR_ARRIVE(m) \
    asm volatile("cp.async.mbarrier.arrive.noinc.shared.b64 [%0];" :: "r"((uint32_t)(m)) : "memory")
#define MBARRIER_WAIT_PARITY(m, p) do { \
    uint32_t _m = (uint32_t)(m), _p = (uint32_t)(p), _d; \
    asm volatile("{\n\t.reg .pred q;\n\t" \
        "mbarrier.try_wait.parity.shared.b64 q, [%1], %2;\n\t" \
        "selp.b32 %0, 1, 0, q;\n\t}" : "=r"(_d) : "r"(_m), "r"(_p) : "memory"); \
    if (!_d) { \
        asm volatile("{\n\t.reg .pred Q;\n\t" \
            "WL_%=:\n\t" \
            "mbarrier.try_wait.parity.shared.b64 Q, [%0], %1;\n\t" \
            "@Q bra.uni WD_%=;\n\t" \
            "bra.uni WL_%=;\n\t" \
            "WD_%=:\n\t}" :: "r"(_m), "r"(_p) : "memory"); \
    } \
} while (0)

__device__ __forceinline__ uint32_t pack_h2(float x, float y) {
    __half2 h = __floats2half2_rn(x, y);
    return *(uint32_t*)&h;
}

// -------- fp32 -> fp16 conversions (vectorized) --------
__global__ void convert_acts_kernel(const float* __restrict__ x, const float* __restrict__ y,
                                    __half* __restrict__ xs, __half* __restrict__ ys) {
    const float* src = blockIdx.y ? y : x;
    __half* dst = blockIdx.y ? ys : xs;
    size_t i = ((size_t)blockIdx.x * blockDim.x + threadIdx.x) * 4;
    float4 v = *(const float4*)(src + i);
    uint2 o;
    o.x = pack_h2(v.x, v.y);
    o.y = pack_h2(v.z, v.w);
    *(uint2*)(dst + i) = o;
}
__global__ void convert_wgts_kernel(const float* __restrict__ Wq, const float* __restrict__ Wk,
                                    const float* __restrict__ Wv, const float* __restrict__ Wo,
                                    __half* __restrict__ wq, __half* __restrict__ wkv,
                                    __half* __restrict__ wo) {
    int sel = blockIdx.y;
    const float* src = (sel == 0) ? Wq : (sel == 1) ? Wk : (sel == 2) ? Wv : Wo;
    __half* dst = (sel == 0) ? wq : (sel == 1) ? wkv
                : (sel == 2) ? wkv + (size_t)C_DIM * C_DIM : wo;
    size_t i = ((size_t)blockIdx.x * blockDim.x + threadIdx.x) * 4;
    float4 v = *(const float4*)(src + i);
    uint2 o;
    o.x = pack_h2(v.x, v.y);
    o.y = pack_h2(v.z, v.w);
    *(uint2*)(dst + i) = o;
}
__global__ void concat_bias_kernel(const float* __restrict__ bk,
                                   const float* __restrict__ bv,
                                   float* __restrict__ dst) {
    int i = blockIdx.x * blockDim.x + threadIdx.x;
    dst[i] = (i < C_DIM) ? bk[i] : bv[i - C_DIM];
}

// -------- warp-specialized HMMA GEMM core (256 thr, 2 CTAs/SM) --------
// Producer: warps 0,1. Each fills half a stage (1024 x 16B chunks, 32/lane).
// Consumers: all 8 warps. full[s]: 64 pre-counted cp.async arrivals.
// empty[s]: 8 warp arrivals (lane 0 after compute).
__device__ __forceinline__ void produce_stage(const __half* __restrict__ A,
                                              const __half* __restrict__ B,
                                              int rowA0, int rowB0, int k0,
                                              uint32_t sbase, int half, int lane) {
#pragma unroll
    for (int it = 0; it < 32; it++) {
        int idx = half * 1024 + it * 32 + lane;
        int row = idx >> 3;
        int c = idx & 7;
        const __half* g = (row < AROWS)
            ? A + (size_t)(rowA0 + row) * KDIM + (k0 + c * 8)
            : B + (size_t)(rowB0 + row - AROWS) * KDIM + (k0 + c * 8);
        CP_ASYNC16(sbase + row * ROW_BYTES + c * 16, g);
    }
}

__device__ __forceinline__ void gemm_core(const __half* __restrict__ A,
                                          const __half* __restrict__ B,
                                          const float* __restrict__ bias,
                                          const float* __restrict__ residual,
                                          float* __restrict__ Cout, int ldc,
                                          int rowA0, int rowB0, char* smem) {
    __shared__ uint64_t mb[2 * STAGES];          // full[0..2], empty[3..5]
    uint32_t sb = smem_u32(smem);
    uint32_t mbb = smem_u32(mb);
    int tid = threadIdx.x;
    int wid = tid >> 5, lid = tid & 31;
    int warp_m = wid & 1;                   // 2 warps over M (64 rows each)
    int warp_n = wid >> 1;                  // 4 warps over N (32 cols each)

    if (tid == 0) {
#pragma unroll
        for (int s = 0; s < STAGES; s++) {
            MBARRIER_INIT(mbb + s * 8, 64);                 // full: 64 producer threads
            MBARRIER_INIT(mbb + (STAGES + s) * 8, 8);       // empty: 8 warps
        }
    }
    __syncthreads();

    float acc[4][4][4];
#pragma unroll
    for (int mi = 0; mi < 4; mi++)
#pragma unroll
        for (int ni = 0; ni < 4; ni++)
#pragma unroll
            for (int e = 0; e < 4; e++) acc[mi][ni][e] = 0.f;

    // prologue: producers fill stages 0..STAGES-2 (known empty, no wait)
    if (wid < 2) {
#pragma unroll
        for (int s = 0; s < STAGES - 1; s++) {
            produce_stage(A, B, rowA0, rowB0, s * BK, sb + s * STAGE_BYTES, wid, lid);
            CP_ASYNC_MBAR_ARRIVE(mbb + s * 8);
        }
    }

    uint32_t a_base = sb + (warp_m * 64 + (lid & 15)) * ROW_BYTES + ((lid >> 4) << 4);
    int g = lid >> 3;
    uint32_t b_base = sb + (AROWS + warp_n * 32 + ((g >> 1) << 3) + (lid & 7)) * ROW_BYTES
                         + ((g & 1) << 4);

    for (int k = 0; k < NKCH; k++) {
        int buf = k % STAGES;
        // consumer: wait for data (fill f = k/STAGES, parity f&1)
        MBARRIER_WAIT_PARITY(mbb + buf * 8, (k / STAGES) & 1);

        // producer: refill stage for chunk k+2 (wait until prior fill consumed)
        int pk = k + STAGES - 1;
        if (wid < 2 && pk < NKCH) {
            int ps = pk % STAGES;
            MBARRIER_WAIT_PARITY(mbb + (STAGES + ps) * 8, 1 ^ ((pk / STAGES) & 1));
            produce_stage(A, B, rowA0, rowB0, pk * BK, sb + ps * STAGE_BYTES, wid, lid);
            CP_ASYNC_MBAR_ARRIVE(mbb + ps * 8);
        }

        uint32_t sa  = a_base + buf * STAGE_BYTES;
        uint32_t sbb = b_base + buf * STAGE_BYTES;
#pragma unroll
        for (int ks = 0; ks < 4; ks++) {    // 4 x k16 per BK=64
            uint32_t afr[4][4], bfr[2][4];
#pragma unroll
            for (int mi = 0; mi < 4; mi++)
                LDSM4(afr[mi], sa + mi * 16 * ROW_BYTES + ks * 32);
#pragma unroll
            for (int ni2 = 0; ni2 < 2; ni2++)
                LDSM4(bfr[ni2], sbb + ni2 * 16 * ROW_BYTES + ks * 32);
#pragma unroll
            for (int mi = 0; mi < 4; mi++)
#pragma unroll
                for (int ni2 = 0; ni2 < 2; ni2++) {
                    MMA16816(acc[mi][2 * ni2],     afr[mi], bfr[ni2][0], bfr[ni2][1]);
                    MMA16816(acc[mi][2 * ni2 + 1], afr[mi], bfr[ni2][2], bfr[ni2][3]);
                }
        }
        // mark stage consumed (MMA issue implies LDSM data is in registers)
        __syncwarp();
        if (lid == 0) MBARRIER_ARRIVE(mbb + (STAGES + buf) * 8);
    }

    int qrow = lid >> 2, qcol = (lid & 3) * 2;
#pragma unroll
    for (int mi = 0; mi < 4; mi++) {
#pragma unroll
        for (int ni = 0; ni < 4; ni++) {
            int r0 = rowA0 + warp_m * 64 + mi * 16 + qrow;
            int col = rowB0 + warp_n * 32 + ni * 8 + qcol;
            float2 bb = *(const float2*)(bias + col);
            float2 v0 = make_float2(acc[mi][ni][0] + bb.x, acc[mi][ni][1] + bb.y);
            float2 v1 = make_float2(acc[mi][ni][2] + bb.x, acc[mi][ni][3] + bb.y);
            if (residual) {
                float2 r0v = *(const float2*)(residual + (size_t)r0 * ldc + col);
                float2 r1v = *(const float2*)(residual + (size_t)(r0 + 8) * ldc + col);
                v0.x += r0v.x; v0.y += r0v.y;
                v1.x += r1v.x; v1.y += r1v.y;
            }
            *(float2*)(Cout + (size_t)r0 * ldc + col) = v0;
            *(float2*)(Cout + (size_t)(r0 + 8) * ldc + col) = v1;
        }
    }
}

// fused Q + KV GEMM: bx < 16 -> Q tile; bx >= 16 -> KV tile
__global__ void __launch_bounds__(GTHREADS, 2)
gemm_qkv_kernel(const __half* __restrict__ xs, const __half* __restrict__ ys,
                const __half* __restrict__ wq, const __half* __restrict__ wkv,
                const float* __restrict__ bq, const float* __restrict__ bkv,
                float* __restrict__ q, float* __restrict__ kv) {
    extern __shared__ __align__(16) char smem[];
    int bx = blockIdx.x;
    if (bx < 16) {
        gemm_core(xs, wq, bq, nullptr, q, C_DIM, blockIdx.y * BM, bx * BN, smem);
    } else {
        gemm_core(ys, wkv, bkv, nullptr, kv, 2 * C_DIM, blockIdx.y * BM, (bx - 16) * BN, smem);
    }
}

__global__ void __launch_bounds__(GTHREADS, 2)
gemm_kernel(const __half* __restrict__ A, const __half* __restrict__ B,
            const float* __restrict__ bias, const float* __restrict__ residual,
            float* __restrict__ Cout, int ldc) {
    extern __shared__ __align__(16) char smem[];
    gemm_core(A, B, bias, residual, Cout, ldc, blockIdx.y * BM, blockIdx.x * BN, smem);
}

// -------- per-token [8x8] head-mixing attention; writes fp16 directly --------
__global__ void __launch_bounds__(256)
attention_kernel(const float* __restrict__ Q, const float* __restrict__ KV,
                 __half* __restrict__ AOS) {
    int lid = threadIdx.x & 31;
    int t = blockIdx.x * 8 + (threadIdx.x >> 5);
    const float4* q  = (const float4*)(Q  + (size_t)t * C_DIM);
    const float4* kv = (const float4*)(KV + (size_t)t * 2 * C_DIM);
    const float scale = 0.0625f;  // 256^-0.5

    for (int h = 0; h < 8; h++) {
        float4 q0 = q[h * 64 + lid * 2];
        float4 q1 = q[h * 64 + lid * 2 + 1];
        float s[8];
#pragma unroll
        for (int gg = 0; gg < 8; gg++) {
            float4 k0 = kv[gg * 64 + lid * 2];
            float4 k1 = kv[gg * 64 + lid * 2 + 1];
            float d = q0.x * k0.x + q0.y * k0.y + q0.z * k0.z + q0.w * k0.w
                    + q1.x * k1.x + q1.y * k1.y + q1.z * k1.z + q1.w * k1.w;
#pragma unroll
            for (int off = 16; off >= 1; off >>= 1)
                d += __shfl_xor_sync(0xffffffffu, d, off);
            s[gg] = d * scale;
        }
        float m = s[0];
#pragma unroll
        for (int gg = 1; gg < 8; gg++) m = fmaxf(m, s[gg]);
        float e[8], sum = 0.f;
#pragma unroll
        for (int gg = 0; gg < 8; gg++) { e[gg] = __expf(s[gg] - m); sum += e[gg]; }
        float inv = 1.f / sum;
        float f[8];
#pragma unroll
        for (int j = 0; j < 8; j++) f[j] = 0.f;
#pragma unroll
        for (int gg = 0; gg < 8; gg++) {
            float p = e[gg] * inv;
            float4 v0 = kv[512 + gg * 64 + lid * 2];
            float4 v1 = kv[512 + gg * 64 + lid * 2 + 1];
            f[0] += p * v0.x; f[1] += p * v0.y; f[2] += p * v0.z; f[3] += p * v0.w;
            f[4] += p * v1.x; f[5] += p * v1.y; f[6] += p * v1.z; f[7] += p * v1.w;
        }
        uint4 H;
        H.x = pack_h2(f[0], f[1]); H.y = pack_h2(f[2], f[3]);
        H.z = pack_h2(f[4], f[5]); H.w = pack_h2(f[6], f[7]);
        size_t base = (size_t)t * C_DIM + h * 256 + lid * 8;
        *(uint4*)(AOS + base) = H;
    }
}

// -------- launch --------
extern "C" void kernel_launch(void* const* d_in, const int* in_sizes, int n_in,
                              void* d_out, int out_size) {
    (void)in_sizes; (void)n_in; (void)out_size;
    const float* x  = (const float*)d_in[0];
    const float* y  = (const float*)d_in[1];
    const float* Wq = (const float*)d_in[2];
    const float* bq = (const float*)d_in[3];
    const float* Wk = (const float*)d_in[4];
    const float* bk = (const float*)d_in[5];
    const float* Wv = (const float*)d_in[6];
    const float* bv = (const float*)d_in[7];
    const float* Wo = (const float*)d_in[8];
    const float* bo = (const float*)d_in[9];
    float* out = (float*)d_out;

    cudaFuncSetAttribute(gemm_kernel, cudaFuncAttributeMaxDynamicSharedMemorySize, GEMM_SMEM);
    cudaFuncSetAttribute(gemm_qkv_kernel, cudaFuncAttributeMaxDynamicSharedMemorySize, GEMM_SMEM);

    __half *xs, *ys, *aos, *wq, *wkv, *wo;
    float *q, *kv, *bkv;
    cudaGetSymbolAddress((void**)&xs,  g_xs);
    cudaGetSymbolAddress((void**)&ys,  g_ys);
    cudaGetSymbolAddress((void**)&aos, g_aos);
    cudaGetSymbolAddress((void**)&wq,  g_wq);
    cudaGetSymbolAddress((void**)&wkv, g_wkv);
    cudaGetSymbolAddress((void**)&wo,  g_wo);
    cudaGetSymbolAddress((void**)&q,   g_q);
    cudaGetSymbolAddress((void**)&kv,  g_kv);
    cudaGetSymbolAddress((void**)&bkv, g_bkv);

    const int actBlocks = (T_TOK * C_DIM) / (256 * 4);   // 8192 per tensor
    const int wgtBlocks = (C_DIM * C_DIM) / (256 * 4);   // 4096 per tensor

    // launch order chosen so ncu (-s 5) profiles the O GEMM (index 5)
    concat_bias_kernel<<<16, 256>>>(bk, bv, bkv);                            // 0
    convert_acts_kernel<<<dim3(actBlocks, 2), 256>>>(x, y, xs, ys);          // 1
    convert_wgts_kernel<<<dim3(wgtBlocks, 4), 256>>>(Wq, Wk, Wv, Wo,
                                                     wq, wkv, wo);           // 2
    gemm_qkv_kernel<<<dim3(48, 64), GTHREADS, GEMM_SMEM>>>(xs, ys, wq, wkv,
                                                           bq, bkv, q, kv);  // 3
    attention_kernel<<<T_TOK / 8, 256>>>(q, kv, aos);                        // 4
    gemm_kernel<<<dim3(16, 64), GTHREADS, GEMM_SMEM>>>(aos, wo, bo, x, out,
                                                       C_DIM);               // 5
}

// round 17
// speedup vs baseline: 1.0985x; 1.0985x over previous
#include <cuda_runtime.h>
#include <cuda_fp16.h>
#include <cstdint>

static constexpr int T_TOK = 8192;
static constexpr int C_DIM = 2048;
static constexpr int KDIM = C_DIM;         // plain fp16 GEMM, K = 2048
static constexpr int BM = 128;
static constexpr int BN = 128;
static constexpr int BK = 64;              // fp16 per K-chunk (128B rows)
static constexpr int NKCH = KDIM / BK;     // 32
static constexpr int ROW_BYTES = 144;      // 128B data + 16B pad (conflict-free ldmatrix)
static constexpr int AROWS = BM;
static constexpr int STAGE_ROWS = BM + BN; // 256
static constexpr int STAGE_BYTES = STAGE_ROWS * ROW_BYTES;  // 36864
static constexpr int STAGES = 3;
static constexpr int GEMM_SMEM = STAGES * STAGE_BYTES;      // 110592 -> 2 CTAs/SM
static constexpr int GTHREADS = 256;       // 8 warps: 2 over M x 4 over N (64x32 tiles)

// -------- scratch (static __device__; no allocation allowed) --------
__device__ __half g_xs [(size_t)T_TOK * C_DIM];
__device__ __half g_ys [(size_t)T_TOK * C_DIM];
__device__ __half g_aos[(size_t)T_TOK * C_DIM];
__device__ __half g_wq [(size_t)C_DIM * C_DIM];
__device__ __half g_wkv[(size_t)(2 * C_DIM) * C_DIM];
__device__ __half g_wo [(size_t)C_DIM * C_DIM];
__device__ __half g_q  [(size_t)T_TOK * C_DIM];          // fp16 q
__device__ __half g_kv [(size_t)T_TOK * 2 * C_DIM];      // fp16 [k|v]
__device__ float g_bkv[2 * C_DIM];

// -------- PTX helpers (sm_80+ only) --------
__device__ __forceinline__ uint32_t smem_u32(const void* p) {
    uint32_t a;
    asm("{ .reg .u64 t; cvta.to.shared.u64 t, %1; cvt.u32.u64 %0, t; }" : "=r"(a) : "l"(p));
    return a;
}
#define CP_ASYNC16(s, g) \
    asm volatile("cp.async.cg.shared.global [%0], [%1], 16;" :: "r"((uint32_t)(s)), "l"(g) : "memory")
#define CP_COMMIT() asm volatile("cp.async.commit_group;" ::: "memory")

#define LDSM4(r, addr) \
    asm volatile("ldmatrix.sync.aligned.m8n8.x4.shared.b16 {%0,%1,%2,%3}, [%4];" \
        : "=r"((r)[0]), "=r"((r)[1]), "=r"((r)[2]), "=r"((r)[3]) : "r"(addr))

#define MMA16816(d, a, b0, b1) \
    asm volatile("mma.sync.aligned.m16n8k16.row.col.f32.f16.f16.f32 " \
        "{%0,%1,%2,%3}, {%4,%5,%6,%7}, {%8,%9}, {%0,%1,%2,%3};" \
        : "+f"((d)[0]), "+f"((d)[1]), "+f"((d)[2]), "+f"((d)[3]) \
        : "r"((a)[0]), "r"((a)[1]), "r"((a)[2]), "r"((a)[3]), "r"(b0), "r"(b1))

__device__ __forceinline__ uint32_t pack_h2(float x, float y) {
    __half2 h = __floats2half2_rn(x, y);
    return *(uint32_t*)&h;
}
__device__ __forceinline__ float2 unpack_h2(uint32_t u) {
    __half2 h = *(__half2*)&u;
    return __half22float2(h);
}

// -------- fp32 -> fp16 conversions (vectorized) --------
__global__ void convert_acts_kernel(const float* __restrict__ x, const float* __restrict__ y,
                                    __half* __restrict__ xs, __half* __restrict__ ys) {
    const float* src = blockIdx.y ? y : x;
    __half* dst = blockIdx.y ? ys : xs;
    size_t i = ((size_t)blockIdx.x * blockDim.x + threadIdx.x) * 4;
    float4 v = *(const float4*)(src + i);
    uint2 o;
    o.x = pack_h2(v.x, v.y);
    o.y = pack_h2(v.z, v.w);
    *(uint2*)(dst + i) = o;
}
__global__ void convert_wgts_kernel(const float* __restrict__ Wq, const float* __restrict__ Wk,
                                    const float* __restrict__ Wv, const float* __restrict__ Wo,
                                    __half* __restrict__ wq, __half* __restrict__ wkv,
                                    __half* __restrict__ wo) {
    int sel = blockIdx.y;
    const float* src = (sel == 0) ? Wq : (sel == 1) ? Wk : (sel == 2) ? Wv : Wo;
    __half* dst = (sel == 0) ? wq : (sel == 1) ? wkv
                : (sel == 2) ? wkv + (size_t)C_DIM * C_DIM : wo;
    size_t i = ((size_t)blockIdx.x * blockDim.x + threadIdx.x) * 4;
    float4 v = *(const float4*)(src + i);
    uint2 o;
    o.x = pack_h2(v.x, v.y);
    o.y = pack_h2(v.z, v.w);
    *(uint2*)(dst + i) = o;
}
__global__ void concat_bias_kernel(const float* __restrict__ bk,
                                   const float* __restrict__ bv,
                                   float* __restrict__ dst) {
    int i = blockIdx.x * blockDim.x + threadIdx.x;
    dst[i] = (i < C_DIM) ? bk[i] : bv[i - C_DIM];
}

// -------- HMMA GEMM core (256 threads, 2 CTAs/SM), R14 pipeline --------
__device__ __forceinline__ void load_tiles_part(const __half* __restrict__ A,
                                                const __half* __restrict__ B,
                                                int rowA0, int rowB0, int k0,
                                                uint32_t sbase, int tid, int part) {
#pragma unroll
    for (int i = 2 * part; i < 2 * part + 2; i++) {
        int idx = i * GTHREADS + tid;
        int row = idx >> 3;
        int c = idx & 7;
        const __half* g = (row < AROWS)
            ? A + (size_t)(rowA0 + row) * KDIM + (k0 + c * 8)
            : B + (size_t)(rowB0 + row - AROWS) * KDIM + (k0 + c * 8);
        CP_ASYNC16(sbase + row * ROW_BYTES + c * 16, g);
    }
}
__device__ __forceinline__ void load_tiles(const __half* __restrict__ A,
                                           const __half* __restrict__ B,
                                           int rowA0, int rowB0, int k0,
                                           uint32_t sbase, int tid) {
#pragma unroll
    for (int p = 0; p < 4; p++)
        load_tiles_part(A, B, rowA0, rowB0, k0, sbase, tid, p);
}

// HALF_OUT: write fp16 output (no residual). Otherwise fp32 (+ optional residual).
template <bool HALF_OUT>
__device__ __forceinline__ void gemm_core(const __half* __restrict__ A,
                                          const __half* __restrict__ B,
                                          const float* __restrict__ bias,
                                          const float* __restrict__ residual,
                                          void* __restrict__ CoutV, int ldc,
                                          int rowA0, int rowB0, char* smem) {
    uint32_t sb = smem_u32(smem);
    int tid = threadIdx.x;
    int wid = tid >> 5, lid = tid & 31;
    int warp_m = wid & 1;                   // 2 warps over M (64 rows each)
    int warp_n = wid >> 1;                  // 4 warps over N (32 cols each)

    float acc[4][4][4];
#pragma unroll
    for (int mi = 0; mi < 4; mi++)
#pragma unroll
        for (int ni = 0; ni < 4; ni++)
#pragma unroll
            for (int e = 0; e < 4; e++) acc[mi][ni][e] = 0.f;

#pragma unroll
    for (int s = 0; s < STAGES - 1; s++) {
        load_tiles(A, B, rowA0, rowB0, s * BK, sb + s * STAGE_BYTES, tid);
        CP_COMMIT();
    }

    uint32_t a_base = sb + (warp_m * 64 + (lid & 15)) * ROW_BYTES + ((lid >> 4) << 4);
    int g = lid >> 3;
    uint32_t b_base = sb + (AROWS + warp_n * 32 + ((g >> 1) << 3) + (lid & 7)) * ROW_BYTES
                         + ((g & 1) << 4);

    for (int k = 0; k < NKCH; k++) {
        int rem = NKCH - 1 - k;
        if (rem > STAGES - 2) rem = STAGES - 2;
        if (rem == 0) asm volatile("cp.async.wait_group 0;" ::: "memory");
        else         asm volatile("cp.async.wait_group 1;" ::: "memory");
        __syncthreads();

        uint32_t sa  = a_base + (k % STAGES) * STAGE_BYTES;
        uint32_t sbb = b_base + (k % STAGES) * STAGE_BYTES;

        int pk = k + STAGES - 1;
        bool do_pf = (pk < NKCH);
        uint32_t pf_base = sb + (pk % STAGES) * STAGE_BYTES;
        int pf_k0 = pk * BK;

#pragma unroll
        for (int ks = 0; ks < 4; ks++) {    // 4 x k16 per BK=64
            uint32_t afr[4][4], bfr[2][4];
#pragma unroll
            for (int mi = 0; mi < 4; mi++)
                LDSM4(afr[mi], sa + mi * 16 * ROW_BYTES + ks * 32);
#pragma unroll
            for (int ni2 = 0; ni2 < 2; ni2++)
                LDSM4(bfr[ni2], sbb + ni2 * 16 * ROW_BYTES + ks * 32);
            // spread prefetch across ks steps
            if (do_pf) {
                load_tiles_part(A, B, rowA0, rowB0, pf_k0, pf_base, tid, ks);
                if (ks == 3) CP_COMMIT();
            }
#pragma unroll
            for (int mi = 0; mi < 4; mi++)
#pragma unroll
                for (int ni2 = 0; ni2 < 2; ni2++) {
                    MMA16816(acc[mi][2 * ni2],     afr[mi], bfr[ni2][0], bfr[ni2][1]);
                    MMA16816(acc[mi][2 * ni2 + 1], afr[mi], bfr[ni2][2], bfr[ni2][3]);
                }
        }
    }

    int qrow = lid >> 2, qcol = (lid & 3) * 2;
#pragma unroll
    for (int mi = 0; mi < 4; mi++) {
#pragma unroll
        for (int ni = 0; ni < 4; ni++) {
            int r0 = rowA0 + warp_m * 64 + mi * 16 + qrow;
            int col = rowB0 + warp_n * 32 + ni * 8 + qcol;
            float2 bb = *(const float2*)(bias + col);
            float2 v0 = make_float2(acc[mi][ni][0] + bb.x, acc[mi][ni][1] + bb.y);
            float2 v1 = make_float2(acc[mi][ni][2] + bb.x, acc[mi][ni][3] + bb.y);
            if constexpr (HALF_OUT) {
                __half* Cout = (__half*)CoutV;
                *(uint32_t*)(Cout + (size_t)r0 * ldc + col) = pack_h2(v0.x, v0.y);
                *(uint32_t*)(Cout + (size_t)(r0 + 8) * ldc + col) = pack_h2(v1.x, v1.y);
            } else {
                float* Cout = (float*)CoutV;
                if (residual) {
                    float2 r0v = *(const float2*)(residual + (size_t)r0 * ldc + col);
                    float2 r1v = *(const float2*)(residual + (size_t)(r0 + 8) * ldc + col);
                    v0.x += r0v.x; v0.y += r0v.y;
                    v1.x += r1v.x; v1.y += r1v.y;
                }
                *(float2*)(Cout + (size_t)r0 * ldc + col) = v0;
                *(float2*)(Cout + (size_t)(r0 + 8) * ldc + col) = v1;
            }
        }
    }
}

// fused Q + KV GEMM (fp16 outputs): bx < 16 -> Q tile; bx >= 16 -> KV tile
__global__ void __launch_bounds__(GTHREADS, 2)
gemm_qkv_kernel(const __half* __restrict__ xs, const __half* __restrict__ ys,
                const __half* __restrict__ wq, const __half* __restrict__ wkv,
                const float* __restrict__ bq, const float* __restrict__ bkv,
                __half* __restrict__ q, __half* __restrict__ kv) {
    extern __shared__ __align__(16) char smem[];
    int bx = blockIdx.x;
    if (bx < 16) {
        gemm_core<true>(xs, wq, bq, nullptr, q, C_DIM, blockIdx.y * BM, bx * BN, smem);
    } else {
        gemm_core<true>(ys, wkv, bkv, nullptr, kv, 2 * C_DIM, blockIdx.y * BM, (bx - 16) * BN, smem);
    }
}

// O GEMM (fp32 output + residual)
__global__ void __launch_bounds__(GTHREADS, 2)
gemm_kernel(const __half* __restrict__ A, const __half* __restrict__ B,
            const float* __restrict__ bias, const float* __restrict__ residual,
            float* __restrict__ Cout, int ldc) {
    extern __shared__ __align__(16) char smem[];
    gemm_core<false>(A, B, bias, residual, Cout, ldc, blockIdx.y * BM, blockIdx.x * BN, smem);
}

// -------- per-token [8x8] head-mixing attention; fp16 in, fp16 out --------
__global__ void __launch_bounds__(256)
attention_kernel(const __half* __restrict__ Q, const __half* __restrict__ KV,
                 __half* __restrict__ AOS) {
    int lid = threadIdx.x & 31;
    int t = blockIdx.x * 8 + (threadIdx.x >> 5);
    const __half* qh  = Q  + (size_t)t * C_DIM;
    const __half* kvh = KV + (size_t)t * 2 * C_DIM;
    const float scale = 0.0625f;  // 256^-0.5

    for (int h = 0; h < 8; h++) {
        // lane's 8 q values (fp16 -> fp32)
        uint4 qv = *(const uint4*)(qh + h * 256 + lid * 8);
        float2 qa = unpack_h2(qv.x), qb = unpack_h2(qv.y);
        float2 qc = unpack_h2(qv.z), qd = unpack_h2(qv.w);
        float s[8];
#pragma unroll
        for (int gg = 0; gg < 8; gg++) {
            uint4 kvv = *(const uint4*)(kvh + gg * 256 + lid * 8);
            float2 ka = unpack_h2(kvv.x), kb = unpack_h2(kvv.y);
            float2 kc = unpack_h2(kvv.z), kd = unpack_h2(kvv.w);
            float d = qa.x * ka.x + qa.y * ka.y + qb.x * kb.x + qb.y * kb.y
                    + qc.x * kc.x + qc.y * kc.y + qd.x * kd.x + qd.y * kd.y;
#pragma unroll
            for (int off = 16; off >= 1; off >>= 1)
                d += __shfl_xor_sync(0xffffffffu, d, off);
            s[gg] = d * scale;
        }
        float m = s[0];
#pragma unroll
        for (int gg = 1; gg < 8; gg++) m = fmaxf(m, s[gg]);
        float e[8], sum = 0.f;
#pragma unroll
        for (int gg = 0; gg < 8; gg++) { e[gg] = __expf(s[gg] - m); sum += e[gg]; }
        float inv = 1.f / sum;
        float f[8];
#pragma unroll
        for (int j = 0; j < 8; j++) f[j] = 0.f;
#pragma unroll
        for (int gg = 0; gg < 8; gg++) {
            float p = e[gg] * inv;
            uint4 vv = *(const uint4*)(kvh + 2048 + gg * 256 + lid * 8);
            float2 va = unpack_h2(vv.x), vb = unpack_h2(vv.y);
            float2 vc = unpack_h2(vv.z), vd = unpack_h2(vv.w);
            f[0] += p * va.x; f[1] += p * va.y; f[2] += p * vb.x; f[3] += p * vb.y;
            f[4] += p * vc.x; f[5] += p * vc.y; f[6] += p * vd.x; f[7] += p * vd.y;
        }
        uint4 H;
        H.x = pack_h2(f[0], f[1]); H.y = pack_h2(f[2], f[3]);
        H.z = pack_h2(f[4], f[5]); H.w = pack_h2(f[6], f[7]);
        size_t base = (size_t)t * C_DIM + h * 256 + lid * 8;
        *(uint4*)(AOS + base) = H;
    }
}

// -------- launch --------
extern "C" void kernel_launch(void* const* d_in, const int* in_sizes, int n_in,
                              void* d_out, int out_size) {
    (void)in_sizes; (void)n_in; (void)out_size;
    const float* x  = (const float*)d_in[0];
    const float* y  = (const float*)d_in[1];
    const float* Wq = (const float*)d_in[2];
    const float* bq = (const float*)d_in[3];
    const float* Wk = (const float*)d_in[4];
    const float* bk = (const float*)d_in[5];
    const float* Wv = (const float*)d_in[6];
    const float* bv = (const float*)d_in[7];
    const float* Wo = (const float*)d_in[8];
    const float* bo = (const float*)d_in[9];
    float* out = (float*)d_out;

    cudaFuncSetAttribute(gemm_kernel, cudaFuncAttributeMaxDynamicSharedMemorySize, GEMM_SMEM);
    cudaFuncSetAttribute(gemm_qkv_kernel, cudaFuncAttributeMaxDynamicSharedMemorySize, GEMM_SMEM);

    __half *xs, *ys, *aos, *wq, *wkv, *wo, *q, *kv;
    float *bkv;
    cudaGetSymbolAddress((void**)&xs,  g_xs);
    cudaGetSymbolAddress((void**)&ys,  g_ys);
    cudaGetSymbolAddress((void**)&aos, g_aos);
    cudaGetSymbolAddress((void**)&wq,  g_wq);
    cudaGetSymbolAddress((void**)&wkv, g_wkv);
    cudaGetSymbolAddress((void**)&wo,  g_wo);
    cudaGetSymbolAddress((void**)&q,   g_q);
    cudaGetSymbolAddress((void**)&kv,  g_kv);
    cudaGetSymbolAddress((void**)&bkv, g_bkv);

    const int actBlocks = (T_TOK * C_DIM) / (256 * 4);   // 8192 per tensor
    const int wgtBlocks = (C_DIM * C_DIM) / (256 * 4);   // 4096 per tensor

    // launch order chosen so ncu (-s 5) profiles the O GEMM (index 5)
    concat_bias_kernel<<<16, 256>>>(bk, bv, bkv);                            // 0
    convert_acts_kernel<<<dim3(actBlocks, 2), 256>>>(x, y, xs, ys);          // 1
    convert_wgts_kernel<<<dim3(wgtBlocks, 4), 256>>>(Wq, Wk, Wv, Wo,
                                                     wq, wkv, wo);           // 2
    gemm_qkv_kernel<<<dim3(48, 64), GTHREADS, GEMM_SMEM>>>(xs, ys, wq, wkv,
                                                           bq, bkv, q, kv);  // 3
    attention_kernel<<<T_TOK / 8, 256>>>(q, kv, aos);                        // 4
    gemm_kernel<<<dim3(16, 64), GTHREADS, GEMM_SMEM>>>(aos, wo, bo, x, out,
                                                       C_DIM);               // 5
}